// round 2
// baseline (speedup 1.0000x reference)
#include <cuda_runtime.h>
#include <math.h>

// ---------------------------------------------------------------------------
// Fixed problem shapes (from reference setup_inputs)
// ---------------------------------------------------------------------------
#define LTOK  32768      // B * D*H*W
#define CCH   96
#define DD    8
#define HH    64
#define WW    64
#define NWIN  64         // (D/8)*(H/8)*(W/8) = 1*8*8
#define NTOK  512        // 8^3 tokens per window
#define HEADS 6
#define HDIM  16
#define CMP   32         // C/3
#define SQZ   3          // C/30
#define HID   384        // 4C
#define QKVN  288        // 3C

// ---------------------------------------------------------------------------
// Scratch (device globals; no allocation anywhere)
// ---------------------------------------------------------------------------
__device__ float g_xn  [LTOK * CCH];          // LN1 out, later reused for LN2 out
__device__ float g_xcf [CCH * LTOK];          // LN1 out, channels-first
__device__ float g_y1cf[CMP * LTOK];          // conv1+gelu out, channels-first
__device__ float g_y2cf[CCH * LTOK];          // conv2 out, channels-first
__device__ float g_pool[CCH];
__device__ float g_att [CCH];                 // channel attention scale
__device__ float g_bias[HEADS * NTOK * NTOK]; // rpbt[rpi] expanded
__device__ float g_qkv [LTOK * QKVN];
__device__ float g_o   [LTOK * CCH];          // attention out (token order)
__device__ float g_xmid[LTOK * CCH];
__device__ float g_h   [LTOK * HID];          // MLP hidden
__device__ float g_tmp [LTOK * CCH];          // proj / fc2 GEMM out

// ---------------------------------------------------------------------------
__device__ __forceinline__ float gelu_f(float x) {
    return 0.5f * x * (1.f + erff(x * 0.70710678118654752f));
}

// token index for (window, in-window position); window depth count == 1
__device__ __forceinline__ int tok_of(int win, int n) {
    int wh = win >> 3, ww = win & 7;
    int nd = n >> 6, nh = (n >> 3) & 7, nw = n & 7;
    return nd * 4096 + (wh * 8 + nh) * 64 + (ww * 8 + nw);
}

// ---------------------------------------------------------------------------
// LayerNorm over C=96: one warp per row
// ---------------------------------------------------------------------------
__global__ void ln_kernel(const float* __restrict__ x, const float* __restrict__ g,
                          const float* __restrict__ b, float* __restrict__ y) {
    int warp = threadIdx.x >> 5, lane = threadIdx.x & 31;
    int row = blockIdx.x * 8 + warp;
    const float* xr = x + row * CCH;
    float v0 = xr[lane], v1 = xr[lane + 32], v2 = xr[lane + 64];
    float s = v0 + v1 + v2;
    #pragma unroll
    for (int o = 16; o; o >>= 1) s += __shfl_xor_sync(0xffffffffu, s, o);
    float mu = s * (1.f / 96.f);
    float d0 = v0 - mu, d1 = v1 - mu, d2 = v2 - mu;
    float q = d0 * d0 + d1 * d1 + d2 * d2;
    #pragma unroll
    for (int o = 16; o; o >>= 1) q += __shfl_xor_sync(0xffffffffu, q, o);
    float rs = rsqrtf(q * (1.f / 96.f) + 1e-5f);
    float* yr = y + row * CCH;
    yr[lane]      = d0 * rs * g[lane]      + b[lane];
    yr[lane + 32] = d1 * rs * g[lane + 32] + b[lane + 32];
    yr[lane + 64] = d2 * rs * g[lane + 64] + b[lane + 64];
}

// ---------------------------------------------------------------------------
// Transpose [L][96] -> [96][L]  (32x32 tiles; 96 = 3*32, L mult of 32)
// ---------------------------------------------------------------------------
__global__ void tocf_kernel(const float* __restrict__ src, float* __restrict__ dst) {
    __shared__ float t[32][33];
    int c0 = blockIdx.x * 32, l0 = blockIdx.y * 32;
    int tx = threadIdx.x, ty = threadIdx.y;   // 32 x 8
    #pragma unroll
    for (int r = 0; r < 4; r++)
        t[ty + r * 8][tx] = src[(size_t)(l0 + ty + r * 8) * CCH + c0 + tx];
    __syncthreads();
    #pragma unroll
    for (int r = 0; r < 4; r++)
        dst[(size_t)(c0 + ty + r * 8) * LTOK + l0 + tx] = t[tx][ty + r * 8];
}

// ---------------------------------------------------------------------------
// Implicit-GEMM 3x3x3 'SAME' conv, channels-first.
//   y[co][l] = act( bias[co] + sum_{ci,tap} W[co][ci*27+tap] * x[ci][nbr(l,tap)] )
// GEMM: M = LTOK (64-wide tiles = one (d,h) row), N = CO, K = 27*CIN.
// Weight layout [CO][CIN][3][3][3] is already row-major in k = ci*27+tap.
// Tiles 64x32xBK16, 256 threads, per-thread 4M x 2N register tile.
// ---------------------------------------------------------------------------
template <int CIN, int CO, int ACT>
__global__ void convgemm_kernel(const float* __restrict__ Wt,
                                const float* __restrict__ bias,
                                const float* __restrict__ xcf,
                                float* __restrict__ ycf) {
    const int K = CIN * 27;
    __shared__ float As[16][68];
    __shared__ float Bs[16][36];
    int tid = threadIdx.x;
    int m0 = blockIdx.x * 64;            // spans w = 0..63 of one (d,h) row
    int n0 = blockIdx.y * 32;
    int d = m0 >> 12, h = (m0 >> 6) & 63;
    int tx = tid & 15, ty = tid >> 4;    // tx: 4 M-rows, ty: 2 N-cols

    float acc[4][2] = {};

    for (int k0 = 0; k0 < K; k0 += 16) {
        // A tile: gather 64 x 16 (coalesced along m for fixed k)
        #pragma unroll
        for (int r = 0; r < 4; r++) {
            int i = tid + r * 256;
            int kk = i >> 6, mm = i & 63;
            int k = k0 + kk;
            int ci = k / 27;
            int tap = k - ci * 27;
            int td = tap / 9;
            int t2 = tap - td * 9;
            int th = t2 / 3;
            int tw = t2 - th * 3;
            int dd = d + td - 1, hh = h + th - 1, ww = mm + tw - 1;
            float v = 0.f;
            if ((unsigned)dd < DD && (unsigned)hh < HH && (unsigned)ww < WW)
                v = xcf[(size_t)ci * LTOK + dd * 4096 + hh * 64 + ww];
            As[kk][mm] = v;
        }
        // B tile: 32 x 16, row-contiguous in k
        #pragma unroll
        for (int r = 0; r < 2; r++) {
            int i = tid + r * 256;
            int nn = i >> 4, kk = i & 15;
            Bs[kk][nn] = Wt[(size_t)(n0 + nn) * K + k0 + kk];
        }
        __syncthreads();
        #pragma unroll
        for (int kk = 0; kk < 16; kk++) {
            float a[4], b[2];
            #pragma unroll
            for (int i = 0; i < 4; i++) a[i] = As[kk][tx * 4 + i];
            #pragma unroll
            for (int j = 0; j < 2; j++) b[j] = Bs[kk][ty * 2 + j];
            #pragma unroll
            for (int i = 0; i < 4; i++)
                #pragma unroll
                for (int j = 0; j < 2; j++) acc[i][j] += a[i] * b[j];
        }
        __syncthreads();
    }

    int m = m0 + tx * 4;
    #pragma unroll
    for (int j = 0; j < 2; j++) {
        int n = n0 + ty * 2 + j;
        float bb = bias[n];
        float4 v;
        v.x = acc[0][j] + bb; v.y = acc[1][j] + bb;
        v.z = acc[2][j] + bb; v.w = acc[3][j] + bb;
        if (ACT == 1) { v.x = gelu_f(v.x); v.y = gelu_f(v.y); v.z = gelu_f(v.z); v.w = gelu_f(v.w); }
        *(float4*)(ycf + (size_t)n * LTOK + m) = v;
    }
}

// ---------------------------------------------------------------------------
// Channel attention: pooled reduce on channels-first conv output + squeeze-excite
// ---------------------------------------------------------------------------
__global__ void poolcf_kernel() {
    __shared__ float red[8];
    int c = blockIdx.x;
    const float* row = g_y2cf + (size_t)c * LTOK;
    float s = 0.f;
    for (int l = threadIdx.x; l < LTOK; l += 256) s += row[l];
    #pragma unroll
    for (int o = 16; o; o >>= 1) s += __shfl_xor_sync(0xffffffffu, s, o);
    if ((threadIdx.x & 31) == 0) red[threadIdx.x >> 5] = s;
    __syncthreads();
    if (threadIdx.x == 0) {
        float t = 0.f;
        #pragma unroll
        for (int i = 0; i < 8; i++) t += red[i];
        g_pool[c] = t;
    }
}

__global__ void chanatt_kernel(const float* __restrict__ ca1_w, const float* __restrict__ ca1_b,
                               const float* __restrict__ ca2_w, const float* __restrict__ ca2_b) {
    __shared__ float p[CCH];
    __shared__ float t[SQZ];
    int c = threadIdx.x;
    p[c] = g_pool[c] * (1.f / (float)LTOK);
    __syncthreads();
    if (c < SQZ) {
        float s = ca1_b[c];
        for (int i = 0; i < CCH; i++) s += ca1_w[c * CCH + i] * p[i];
        t[c] = fmaxf(s, 0.f);
    }
    __syncthreads();
    float s = ca2_b[c];
    #pragma unroll
    for (int i = 0; i < SQZ; i++) s += ca2_w[c * SQZ + i] * t[i];
    g_att[c] = 1.f / (1.f + expf(-s));
}

// ---------------------------------------------------------------------------
// Relative position bias expand: bias[h][n][m] = rpbt[rpi[n][m]][h]
// ---------------------------------------------------------------------------
__global__ void bias_kernel(const int* __restrict__ rpi, const float* __restrict__ rpbt) {
    int nm = blockIdx.x * blockDim.x + threadIdx.x;
    if (nm >= NTOK * NTOK) return;
    int rp = rpi[nm];
    #pragma unroll
    for (int hh = 0; hh < HEADS; hh++)
        g_bias[hh * NTOK * NTOK + nm] = rpbt[rp * HEADS + hh];
}

// ---------------------------------------------------------------------------
// Generic tiled SGEMM:  C[M,N] = A[M,K] * B[N,K]^T + bias[N]   (+optional GELU)
// 64x64 tile, BK=16, 256 threads, 4x4 per thread.  K must be multiple of 16.
// ---------------------------------------------------------------------------
template <int ACT>
__global__ void sgemm_kernel(const float* __restrict__ A, const float* __restrict__ B,
                             const float* __restrict__ bias, float* __restrict__ C,
                             int M, int N, int K) {
    __shared__ float As[16][68];
    __shared__ float Bs[16][68];
    int tid = threadIdx.x;
    int m0 = blockIdx.y * 64, n0 = blockIdx.x * 64;
    int tx = tid & 15, ty = tid >> 4;
    float acc[4][4] = {};
    for (int k0 = 0; k0 < K; k0 += 16) {
        #pragma unroll
        for (int i = tid; i < 1024; i += 256) {
            int mm = i >> 4, kk = i & 15;
            As[kk][mm] = (m0 + mm < M) ? A[(size_t)(m0 + mm) * K + k0 + kk] : 0.f;
            Bs[kk][mm] = (n0 + mm < N) ? B[(size_t)(n0 + mm) * K + k0 + kk] : 0.f;
        }
        __syncthreads();
        #pragma unroll
        for (int kk = 0; kk < 16; kk++) {
            float a[4], bb[4];
            #pragma unroll
            for (int i = 0; i < 4; i++) a[i] = As[kk][ty * 4 + i];
            #pragma unroll
            for (int j = 0; j < 4; j++) bb[j] = Bs[kk][tx * 4 + j];
            #pragma unroll
            for (int i = 0; i < 4; i++)
                #pragma unroll
                for (int j = 0; j < 4; j++) acc[i][j] += a[i] * bb[j];
        }
        __syncthreads();
    }
    #pragma unroll
    for (int i = 0; i < 4; i++) {
        int m = m0 + ty * 4 + i;
        if (m >= M) continue;
        #pragma unroll
        for (int j = 0; j < 4; j++) {
            int n = n0 + tx * 4 + j;
            if (n >= N) continue;
            float v = acc[i][j] + bias[n];
            if (ACT == 1) v = gelu_f(v);
            C[(size_t)m * N + n] = v;
        }
    }
}

// ---------------------------------------------------------------------------
// Window attention: one block per (window, head), 256 threads.
// K transposed in smem (conflict-free score dots), V row-major, 16-query tiles.
// Dynamic smem layout: skT[16][512] | sv[512][16] | sq[16][16] | ss[16][512]
// ---------------------------------------------------------------------------
__global__ void attn_kernel() {
    int win = blockIdx.x, head = blockIdx.y;
    extern __shared__ float sm[];
    float* skT = sm;                      // 16*512
    float* sv  = skT + HDIM * NTOK;       // 512*16
    float* sq  = sv + NTOK * HDIM;        // 16*16
    float* ss  = sq + 256;                // 16*512
    int tid = threadIdx.x;

    // load K (transposed) and V
    #pragma unroll
    for (int r = 0; r < 2; r++) {
        int n = tid + r * 256;
        int l = tok_of(win, n);
        const float4* kp = (const float4*)(g_qkv + (size_t)l * QKVN + CCH + head * HDIM);
        const float4* vp = (const float4*)(g_qkv + (size_t)l * QKVN + 2 * CCH + head * HDIM);
        #pragma unroll
        for (int j = 0; j < 4; j++) {
            float4 kk = kp[j];
            int e = j * 4;
            skT[(e + 0) * NTOK + n] = kk.x;
            skT[(e + 1) * NTOK + n] = kk.y;
            skT[(e + 2) * NTOK + n] = kk.z;
            skT[(e + 3) * NTOK + n] = kk.w;
            ((float4*)(sv + n * HDIM))[j] = vp[j];
        }
    }
    __syncthreads();

    const float* brow = g_bias + (size_t)head * NTOK * NTOK;

    for (int qt = 0; qt < NTOK / 16; qt++) {
        // load 16 q rows (scaled by hd^-0.5 = 0.25)
        {
            int qi = tid >> 4, e = tid & 15;
            int n = qt * 16 + qi;
            int l = tok_of(win, n);
            sq[qi * 16 + e] = g_qkv[(size_t)l * QKVN + head * HDIM + e] * 0.25f;
        }
        __syncthreads();

        // scores S[16][512] + bias
        for (int i = tid; i < 16 * NTOK; i += 256) {
            int qi = i >> 9, m = i & 511;
            float d = 0.f;
            #pragma unroll
            for (int e = 0; e < HDIM; e++) d += sq[qi * 16 + e] * skT[e * NTOK + m];
            ss[i] = d + brow[(size_t)(qt * 16 + qi) * NTOK + m];
        }
        __syncthreads();

        // softmax per row: 8 warps x 2 rows
        {
            int warp = tid >> 5, lane = tid & 31;
            #pragma unroll
            for (int r = 0; r < 2; r++) {
                float* row = ss + (warp * 2 + r) * NTOK;
                float mx = -3.0e38f;
                #pragma unroll
                for (int m = lane; m < NTOK; m += 32) mx = fmaxf(mx, row[m]);
                #pragma unroll
                for (int o = 16; o; o >>= 1) mx = fmaxf(mx, __shfl_xor_sync(0xffffffffu, mx, o));
                float sum = 0.f;
                #pragma unroll
                for (int m = lane; m < NTOK; m += 32) {
                    float e = __expf(row[m] - mx);
                    row[m] = e;
                    sum += e;
                }
                #pragma unroll
                for (int o = 16; o; o >>= 1) sum += __shfl_xor_sync(0xffffffffu, sum, o);
                float inv = 1.f / sum;
                #pragma unroll
                for (int m = lane; m < NTOK; m += 32) row[m] *= inv;
            }
        }
        __syncthreads();

        // O[16][16] = P[16][512] @ V[512][16]
        {
            int qi = tid >> 4, e = tid & 15;
            const float* prow = ss + qi * NTOK;
            float acc = 0.f;
            #pragma unroll 4
            for (int m = 0; m < NTOK; m++) acc += prow[m] * sv[m * HDIM + e];
            int n = qt * 16 + qi;
            int l = tok_of(win, n);
            g_o[(size_t)l * CCH + head * HDIM + e] = acc;
        }
        __syncthreads();
    }
}

// ---------------------------------------------------------------------------
// Residual 1: xmid = x + proj(attn) + conv_out * a[c] * 0.01
// ---------------------------------------------------------------------------
__global__ void resid1_kernel(const float* __restrict__ x) {
    int i = blockIdx.x * blockDim.x + threadIdx.x;
    if (i >= LTOK * CCH) return;
    int c = i % CCH;
    int l = i / CCH;
    g_xmid[i] = x[i] + g_tmp[i] + g_y2cf[(size_t)c * LTOK + l] * g_att[c] * 0.01f;
}

__global__ void final_kernel(float* __restrict__ out) {
    int i = blockIdx.x * blockDim.x + threadIdx.x;
    if (i >= LTOK * CCH) return;
    out[i] = g_xmid[i] + g_tmp[i];
}

// ---------------------------------------------------------------------------
extern "C" void kernel_launch(void* const* d_in, const int* in_sizes, int n_in,
                              void* d_out, int out_size) {
    const float* x       = (const float*)d_in[0];
    const float* norm1_g = (const float*)d_in[1];
    const float* norm1_b = (const float*)d_in[2];
    const float* qkv_w   = (const float*)d_in[3];
    const float* qkv_b   = (const float*)d_in[4];
    const float* rpbt    = (const float*)d_in[5];
    const float* proj_w  = (const float*)d_in[6];
    const float* proj_b  = (const float*)d_in[7];
    const float* conv1_w = (const float*)d_in[8];
    const float* conv1_b = (const float*)d_in[9];
    const float* conv2_w = (const float*)d_in[10];
    const float* conv2_b = (const float*)d_in[11];
    const float* ca1_w   = (const float*)d_in[12];
    const float* ca1_b   = (const float*)d_in[13];
    const float* ca2_w   = (const float*)d_in[14];
    const float* ca2_b   = (const float*)d_in[15];
    const float* norm2_g = (const float*)d_in[16];
    const float* norm2_b = (const float*)d_in[17];
    const float* fc1_w   = (const float*)d_in[18];
    const float* fc1_b   = (const float*)d_in[19];
    const float* fc2_w   = (const float*)d_in[20];
    const float* fc2_b   = (const float*)d_in[21];
    const int*   rpi     = (const int*)d_in[22];
    float* out = (float*)d_out;

    // pointers to device globals
    float *p_xn, *p_xcf, *p_y1cf, *p_y2cf;
    cudaGetSymbolAddress((void**)&p_xn,   g_xn);
    cudaGetSymbolAddress((void**)&p_xcf,  g_xcf);
    cudaGetSymbolAddress((void**)&p_y1cf, g_y1cf);
    cudaGetSymbolAddress((void**)&p_y2cf, g_y2cf);
    float *p_qkv, *p_o, *p_tmp, *p_h;
    cudaGetSymbolAddress((void**)&p_qkv, g_qkv);
    cudaGetSymbolAddress((void**)&p_o,   g_o);
    cudaGetSymbolAddress((void**)&p_tmp, g_tmp);
    cudaGetSymbolAddress((void**)&p_h,   g_h);
    float *p_xmid;
    cudaGetSymbolAddress((void**)&p_xmid, g_xmid);

    // attention kernel needs ~97 KB dynamic smem
    static const size_t attn_smem =
        (size_t)(HDIM * NTOK + NTOK * HDIM + 256 + 16 * NTOK) * sizeof(float);
    cudaFuncSetAttribute(attn_kernel, cudaFuncAttributeMaxDynamicSharedMemorySize,
                         (int)attn_smem);

    // bias expansion (reads inputs only)
    bias_kernel<<<(NTOK * NTOK + 255) / 256, 256>>>(rpi, rpbt);

    // LN1
    ln_kernel<<<LTOK / 8, 256>>>(x, norm1_g, norm1_b, p_xn);

    // channels-first copy for conv branch
    {
        dim3 grid(CCH / 32, LTOK / 32);
        tocf_kernel<<<grid, dim3(32, 8)>>>(p_xn, p_xcf);
    }

    // conv branch: implicit GEMM convs
    {
        dim3 g1(LTOK / 64, CMP / 32);
        convgemm_kernel<CCH, CMP, 1><<<g1, 256>>>(conv1_w, conv1_b, p_xcf, p_y1cf);
        dim3 g2(LTOK / 64, CCH / 32);
        convgemm_kernel<CMP, CCH, 0><<<g2, 256>>>(conv2_w, conv2_b, p_y1cf, p_y2cf);
    }
    poolcf_kernel<<<CCH, 256>>>();
    chanatt_kernel<<<1, CCH>>>(ca1_w, ca1_b, ca2_w, ca2_b);

    // QKV GEMM: [32768,96] x [288,96]^T
    {
        dim3 grid((QKVN + 63) / 64, (LTOK + 63) / 64);
        sgemm_kernel<0><<<grid, 256>>>(p_xn, qkv_w, qkv_b, p_qkv, LTOK, QKVN, CCH);
    }

    // windowed attention
    {
        dim3 grid(NWIN, HEADS);
        attn_kernel<<<grid, 256, attn_smem>>>();
    }

    // proj GEMM
    {
        dim3 grid((CCH + 63) / 64, (LTOK + 63) / 64);
        sgemm_kernel<0><<<grid, 256>>>(p_o, proj_w, proj_b, p_tmp, LTOK, CCH, CCH);
    }

    // residual 1
    resid1_kernel<<<(LTOK * CCH + 255) / 256, 256>>>(x);

    // LN2 (reuse g_xn)
    ln_kernel<<<LTOK / 8, 256>>>(p_xmid, norm2_g, norm2_b, p_xn);

    // MLP: fc1 (+GELU) then fc2
    {
        dim3 grid((HID + 63) / 64, (LTOK + 63) / 64);
        sgemm_kernel<1><<<grid, 256>>>(p_xn, fc1_w, fc1_b, p_h, LTOK, HID, CCH);
    }
    {
        dim3 grid((CCH + 63) / 64, (LTOK + 63) / 64);
        sgemm_kernel<0><<<grid, 256>>>(p_h, fc2_w, fc2_b, p_tmp, LTOK, CCH, HID);
    }

    // final residual -> output
    final_kernel<<<(LTOK * CCH + 255) / 256, 256>>>(out);
}

// round 9
// speedup vs baseline: 1.4499x; 1.4499x over previous
#include <cuda_runtime.h>
#include <math.h>

// ---------------------------------------------------------------------------
// Fixed problem shapes (from reference setup_inputs)
// ---------------------------------------------------------------------------
#define LTOK  32768      // B * D*H*W
#define CCH   96
#define DD    8
#define HH    64
#define WW    64
#define NWIN  64         // (D/8)*(H/8)*(W/8) = 1*8*8
#define NTOK  512        // 8^3 tokens per window
#define HEADS 6
#define HDIM  16
#define CMP   32         // C/3
#define SQZ   3          // C/30
#define HID   384        // 4C
#define QKVN  288        // 3C

// ---------------------------------------------------------------------------
// Scratch (device globals; no allocation anywhere)
// ---------------------------------------------------------------------------
__device__ float g_xn  [LTOK * CCH];          // LN1 out, later reused for LN2 out
__device__ float g_xcf [CCH * LTOK];          // LN1 out, channels-first
__device__ float g_y1cf[CMP * LTOK];          // conv1+gelu out, channels-first
__device__ float g_y2cf[CCH * LTOK];          // conv2 out, channels-first
__device__ float g_w1t [27 * CMP * CCH];      // conv1 W as [tap][co][ci]
__device__ float g_w2t [27 * CCH * CMP];      // conv2 W as [tap][co][ci]
__device__ float g_pool[CCH];
__device__ float g_att [CCH];                 // channel attention scale
__device__ float g_bias[HEADS * NTOK * NTOK]; // rpbt[rpi] expanded
__device__ float g_qkv [LTOK * QKVN];
__device__ float g_o   [LTOK * CCH];          // attention out (token order)
__device__ float g_xmid[LTOK * CCH];
__device__ float g_h   [LTOK * HID];          // MLP hidden
__device__ float g_tmp [LTOK * CCH];          // proj GEMM out

// ---------------------------------------------------------------------------
__device__ __forceinline__ float gelu_f(float x) {
    return 0.5f * x * (1.f + erff(x * 0.70710678118654752f));
}

// token index for (window, in-window position); window depth count == 1
__device__ __forceinline__ int tok_of(int win, int n) {
    int wh = win >> 3, ww = win & 7;
    int nd = n >> 6, nh = (n >> 3) & 7, nw = n & 7;
    return nd * 4096 + (wh * 8 + nh) * 64 + (ww * 8 + nw);
}

// ---------------------------------------------------------------------------
// LayerNorm over C=96: one warp per row
// ---------------------------------------------------------------------------
__global__ void ln_kernel(const float* __restrict__ x, const float* __restrict__ g,
                          const float* __restrict__ b, float* __restrict__ y) {
    int warp = threadIdx.x >> 5, lane = threadIdx.x & 31;
    int row = blockIdx.x * 8 + warp;
    const float* xr = x + row * CCH;
    float v0 = xr[lane], v1 = xr[lane + 32], v2 = xr[lane + 64];
    float s = v0 + v1 + v2;
    #pragma unroll
    for (int o = 16; o; o >>= 1) s += __shfl_xor_sync(0xffffffffu, s, o);
    float mu = s * (1.f / 96.f);
    float d0 = v0 - mu, d1 = v1 - mu, d2 = v2 - mu;
    float q = d0 * d0 + d1 * d1 + d2 * d2;
    #pragma unroll
    for (int o = 16; o; o >>= 1) q += __shfl_xor_sync(0xffffffffu, q, o);
    float rs = rsqrtf(q * (1.f / 96.f) + 1e-5f);
    float* yr = y + row * CCH;
    yr[lane]      = d0 * rs * g[lane]      + b[lane];
    yr[lane + 32] = d1 * rs * g[lane + 32] + b[lane + 32];
    yr[lane + 64] = d2 * rs * g[lane + 64] + b[lane + 64];
}

// ---------------------------------------------------------------------------
// Fused residual-1 + LayerNorm2: one warp per row.
//   xmid = x + proj_out + conv_out * att[c] * 0.01 ;  xn = LN(xmid)
// ---------------------------------------------------------------------------
__global__ void resid_ln_kernel(const float* __restrict__ x,
                                const float* __restrict__ g, const float* __restrict__ b) {
    int warp = threadIdx.x >> 5, lane = threadIdx.x & 31;
    int row = blockIdx.x * 8 + warp;
    int c0 = lane, c1 = lane + 32, c2 = lane + 64;
    size_t base = (size_t)row * CCH;
    float v0 = x[base + c0] + g_tmp[base + c0] + g_y2cf[(size_t)c0 * LTOK + row] * g_att[c0] * 0.01f;
    float v1 = x[base + c1] + g_tmp[base + c1] + g_y2cf[(size_t)c1 * LTOK + row] * g_att[c1] * 0.01f;
    float v2 = x[base + c2] + g_tmp[base + c2] + g_y2cf[(size_t)c2 * LTOK + row] * g_att[c2] * 0.01f;
    g_xmid[base + c0] = v0; g_xmid[base + c1] = v1; g_xmid[base + c2] = v2;
    float s = v0 + v1 + v2;
    #pragma unroll
    for (int o = 16; o; o >>= 1) s += __shfl_xor_sync(0xffffffffu, s, o);
    float mu = s * (1.f / 96.f);
    float d0 = v0 - mu, d1 = v1 - mu, d2 = v2 - mu;
    float q = d0 * d0 + d1 * d1 + d2 * d2;
    #pragma unroll
    for (int o = 16; o; o >>= 1) q += __shfl_xor_sync(0xffffffffu, q, o);
    float rs = rsqrtf(q * (1.f / 96.f) + 1e-5f);
    g_xn[base + c0] = d0 * rs * g[c0] + b[c0];
    g_xn[base + c1] = d1 * rs * g[c1] + b[c1];
    g_xn[base + c2] = d2 * rs * g[c2] + b[c2];
}

// ---------------------------------------------------------------------------
// Transpose [L][96] -> [96][L]  (32x32 tiles)
// ---------------------------------------------------------------------------
__global__ void tocf_kernel(const float* __restrict__ src, float* __restrict__ dst) {
    __shared__ float t[32][33];
    int c0 = blockIdx.x * 32, l0 = blockIdx.y * 32;
    int tx = threadIdx.x, ty = threadIdx.y;   // 32 x 8
    #pragma unroll
    for (int r = 0; r < 4; r++)
        t[ty + r * 8][tx] = src[(size_t)(l0 + ty + r * 8) * CCH + c0 + tx];
    __syncthreads();
    #pragma unroll
    for (int r = 0; r < 4; r++)
        dst[(size_t)(c0 + ty + r * 8) * LTOK + l0 + tx] = t[tx][ty + r * 8];
}

// ---------------------------------------------------------------------------
// Conv weight transpose: [CO][CI][27] -> [tap][CO][CI]
// ---------------------------------------------------------------------------
__global__ void twc_kernel(const float* __restrict__ w, float* __restrict__ dst,
                           int CO_, int CI_) {
    int i = blockIdx.x * blockDim.x + threadIdx.x;
    if (i >= CO_ * CI_ * 27) return;
    int co = i / (CI_ * 27);
    int rem = i - co * CI_ * 27;
    int ci = rem / 27;
    int tap = rem - ci * 27;
    dst[((size_t)tap * CO_ + co) * CI_ + ci] = w[i];
}

// ---------------------------------------------------------------------------
// Staged load for conv iteration t (t indexes the flattened (tap, kc) loop):
// each thread loads its 8 A-gather values and 2 B values into registers.
// ---------------------------------------------------------------------------
template <int CIN, int CO>
__device__ __forceinline__ void conv_stage_load(
    int t, int tid, int d, int h0, int n0,
    const float* __restrict__ Wt, const float* __restrict__ xcf,
    float* __restrict__ sa, float* __restrict__ sb) {
    const int KCI = CIN / 16;
    int tap = t / KCI;
    int kc = (t - tap * KCI) * 16;
    int td = tap / 9;
    int t2 = tap - td * 9;
    int th = t2 / 3;
    int tw = t2 - th * 3;
    int dd = d + td - 1;
    bool okd = (unsigned)dd < DD;
    int hb = h0 + th - 1;
    bool okh0 = okd && ((unsigned)hb < HH);
    bool okh1 = okd && ((unsigned)(hb + 1) < HH);
    int baseL = dd * 4096 + hb * 64 + (tw - 1);
    const float* wtap = Wt + (size_t)tap * CO * CIN;
    #pragma unroll
    for (int rr = 0; rr < 8; rr++) {
        int i = rr * 256 + tid;
        int kk = i >> 7, mm = i & 127;
        int w = mm & 63;
        bool ok = ((mm >> 6) ? okh1 : okh0) && ((unsigned)(w + tw - 1) < WW);
        sa[rr] = ok ? xcf[(size_t)(kc + kk) * LTOK + baseL + mm] : 0.f;
    }
    #pragma unroll
    for (int rr = 0; rr < 2; rr++) {
        int i = rr * 256 + tid;
        int nn = i >> 4, kk = i & 15;
        sb[rr] = wtap[(size_t)(n0 + nn) * CIN + kc + kk];
    }
}

// ---------------------------------------------------------------------------
// Tap-outer implicit-GEMM 3x3x3 'SAME' conv, channels-first, register-staged
// double buffering (next iteration's gather overlaps compute).
// Tile: 128 M (two (d,h) rows of w) x 32 N.  256 threads, 4x4 per thread.
// ---------------------------------------------------------------------------
template <int CIN, int CO, int ACT>
__global__ void __launch_bounds__(256, 2)
convgemm2_kernel(const float* __restrict__ Wt,
                 const float* __restrict__ bias,
                 const float* __restrict__ xcf,
                 float* __restrict__ ycf) {
    __shared__ float As[16][132];
    __shared__ float Bs[16][36];
    int tid = threadIdx.x;
    int m0 = blockIdx.x * 128;           // two w-rows: (d, h0) and (d, h0+1)
    int n0 = blockIdx.y * 32;
    int d = m0 >> 12;
    int h0 = (m0 >> 6) & 63;
    int tx = tid & 7, ty = tid >> 3;     // tx: 4 N-cols, ty: 4 M-rows

    float acc[4][4] = {};
    const int T = 27 * (CIN / 16);

    float sa[8], sb[2];
    conv_stage_load<CIN, CO>(0, tid, d, h0, n0, Wt, xcf, sa, sb);

    for (int t = 0; t < T; t++) {
        // staged registers -> smem
        #pragma unroll
        for (int rr = 0; rr < 8; rr++) {
            int i = rr * 256 + tid;
            As[i >> 7][i & 127] = sa[rr];
        }
        #pragma unroll
        for (int rr = 0; rr < 2; rr++) {
            int i = rr * 256 + tid;
            Bs[i & 15][i >> 4] = sb[rr];
        }
        __syncthreads();

        // issue next iteration's loads (latency overlapped with compute)
        if (t + 1 < T)
            conv_stage_load<CIN, CO>(t + 1, tid, d, h0, n0, Wt, xcf, sa, sb);

        #pragma unroll
        for (int kk = 0; kk < 16; kk++) {
            float4 a = *(const float4*)&As[kk][ty * 4];
            float4 b = *(const float4*)&Bs[kk][tx * 4];
            float av[4] = {a.x, a.y, a.z, a.w};
            float bv[4] = {b.x, b.y, b.z, b.w};
            #pragma unroll
            for (int i = 0; i < 4; i++)
                #pragma unroll
                for (int j = 0; j < 4; j++) acc[i][j] += av[i] * bv[j];
        }
        __syncthreads();
    }

    // epilogue: float4 store per output channel (m-contiguous)
    int m = m0 + ty * 4;
    #pragma unroll
    for (int j = 0; j < 4; j++) {
        int n = n0 + tx * 4 + j;
        float bb = bias[n];
        float4 v;
        v.x = acc[0][j] + bb; v.y = acc[1][j] + bb;
        v.z = acc[2][j] + bb; v.w = acc[3][j] + bb;
        if (ACT == 1) { v.x = gelu_f(v.x); v.y = gelu_f(v.y); v.z = gelu_f(v.z); v.w = gelu_f(v.w); }
        *(float4*)(ycf + (size_t)n * LTOK + m) = v;
    }
}

// ---------------------------------------------------------------------------
// Channel attention: pooled reduce on channels-first conv output + squeeze-excite
// ---------------------------------------------------------------------------
__global__ void poolcf_kernel() {
    __shared__ float red[8];
    int c = blockIdx.x;
    const float* row = g_y2cf + (size_t)c * LTOK;
    float s = 0.f;
    for (int l = threadIdx.x; l < LTOK; l += 256) s += row[l];
    #pragma unroll
    for (int o = 16; o; o >>= 1) s += __shfl_xor_sync(0xffffffffu, s, o);
    if ((threadIdx.x & 31) == 0) red[threadIdx.x >> 5] = s;
    __syncthreads();
    if (threadIdx.x == 0) {
        float t = 0.f;
        #pragma unroll
        for (int i = 0; i < 8; i++) t += red[i];
        g_pool[c] = t;
    }
}

__global__ void chanatt_kernel(const float* __restrict__ ca1_w, const float* __restrict__ ca1_b,
                               const float* __restrict__ ca2_w, const float* __restrict__ ca2_b) {
    __shared__ float p[CCH];
    __shared__ float t[SQZ];
    int c = threadIdx.x;
    p[c] = g_pool[c] * (1.f / (float)LTOK);
    __syncthreads();
    if (c < SQZ) {
        float s = ca1_b[c];
        for (int i = 0; i < CCH; i++) s += ca1_w[c * CCH + i] * p[i];
        t[c] = fmaxf(s, 0.f);
    }
    __syncthreads();
    float s = ca2_b[c];
    #pragma unroll
    for (int i = 0; i < SQZ; i++) s += ca2_w[c * SQZ + i] * t[i];
    g_att[c] = 1.f / (1.f + expf(-s));
}

// ---------------------------------------------------------------------------
// Relative position bias expand: bias[h][n][m] = rpbt[rpi[n][m]][h]
// ---------------------------------------------------------------------------
__global__ void bias_kernel(const int* __restrict__ rpi, const float* __restrict__ rpbt) {
    int nm = blockIdx.x * blockDim.x + threadIdx.x;
    if (nm >= NTOK * NTOK) return;
    int rp = rpi[nm];
    #pragma unroll
    for (int hh = 0; hh < HEADS; hh++)
        g_bias[hh * NTOK * NTOK + nm] = rpbt[rp * HEADS + hh];
}

// ---------------------------------------------------------------------------
// SGEMM 128x64x16, 256 threads, 8x4 per thread, float4 smem paths,
// register-staged double buffering (next tile's LDGs overlap compute).
//   C[M,N] = A[M,K] @ B[N,K]^T + bias[N]  (+GELU, +residual)
// M must be a multiple of 128; N a multiple of 4; K a multiple of 16.
// ---------------------------------------------------------------------------
template <int ACT, int RESID>
__global__ void __launch_bounds__(256, 2)
sgemm128_kernel(const float* __restrict__ A, const float* __restrict__ B,
                const float* __restrict__ bias, const float* __restrict__ resid,
                float* __restrict__ C, int M, int N, int K) {
    __shared__ float As[16][132];
    __shared__ float Bs[16][68];
    int tid = threadIdx.x;
    int m0 = blockIdx.y * 128, n0 = blockIdx.x * 64;
    int tx = tid & 15, ty = tid >> 4;        // tx: 4 N-cols, ty: 8 M-rows

    int la_m = tid >> 2;                     // 0..63
    int la_k = (tid & 3) * 4;
    bool bn_ok = (n0 + la_m < N);
    float acc[8][4] = {};

    // stage tile 0
    float4 a_pre0 = *(const float4*)(A + (size_t)(m0 + la_m) * K + la_k);
    float4 a_pre1 = *(const float4*)(A + (size_t)(m0 + la_m + 64) * K + la_k);
    float4 b_pre = make_float4(0.f, 0.f, 0.f, 0.f);
    if (bn_ok) b_pre = *(const float4*)(B + (size_t)(n0 + la_m) * K + la_k);

    for (int k0 = 0; k0 < K; k0 += 16) {
        // staged registers -> smem
        As[la_k + 0][la_m] = a_pre0.x;
        As[la_k + 1][la_m] = a_pre0.y;
        As[la_k + 2][la_m] = a_pre0.z;
        As[la_k + 3][la_m] = a_pre0.w;
        As[la_k + 0][la_m + 64] = a_pre1.x;
        As[la_k + 1][la_m + 64] = a_pre1.y;
        As[la_k + 2][la_m + 64] = a_pre1.z;
        As[la_k + 3][la_m + 64] = a_pre1.w;
        Bs[la_k + 0][la_m] = b_pre.x;
        Bs[la_k + 1][la_m] = b_pre.y;
        Bs[la_k + 2][la_m] = b_pre.z;
        Bs[la_k + 3][la_m] = b_pre.w;
        __syncthreads();

        // issue next tile's loads (latency overlapped with compute below)
        if (k0 + 16 < K) {
            int kn = k0 + 16 + la_k;
            a_pre0 = *(const float4*)(A + (size_t)(m0 + la_m) * K + kn);
            a_pre1 = *(const float4*)(A + (size_t)(m0 + la_m + 64) * K + kn);
            if (bn_ok) b_pre = *(const float4*)(B + (size_t)(n0 + la_m) * K + kn);
        }

        #pragma unroll
        for (int kk = 0; kk < 16; kk++) {
            float4 a0 = *(const float4*)&As[kk][ty * 8];
            float4 a1 = *(const float4*)&As[kk][ty * 8 + 4];
            float4 b0 = *(const float4*)&Bs[kk][tx * 4];
            float av[8] = {a0.x, a0.y, a0.z, a0.w, a1.x, a1.y, a1.z, a1.w};
            float bv[4] = {b0.x, b0.y, b0.z, b0.w};
            #pragma unroll
            for (int i = 0; i < 8; i++)
                #pragma unroll
                for (int j = 0; j < 4; j++) acc[i][j] += av[i] * bv[j];
        }
        __syncthreads();
    }

    int n = n0 + tx * 4;
    if (n < N) {
        float4 bb = *(const float4*)(bias + n);
        #pragma unroll
        for (int i = 0; i < 8; i++) {
            int m = m0 + ty * 8 + i;
            float4 v;
            v.x = acc[i][0] + bb.x; v.y = acc[i][1] + bb.y;
            v.z = acc[i][2] + bb.z; v.w = acc[i][3] + bb.w;
            if (ACT == 1) {
                v.x = gelu_f(v.x); v.y = gelu_f(v.y);
                v.z = gelu_f(v.z); v.w = gelu_f(v.w);
            }
            if (RESID == 1) {
                float4 rr = *(const float4*)(resid + (size_t)m * N + n);
                v.x += rr.x; v.y += rr.y; v.z += rr.z; v.w += rr.w;
            }
            *(float4*)(C + (size_t)m * N + n) = v;
        }
    }
}

// ---------------------------------------------------------------------------
// Window attention: one block per (window, head), 256 threads.
// skT[16][512] (K transposed), sv[512][16], ss[16][512].
// Scores: fixed qi per thread, Q in registers, float2 K reads.
// PV: (qi, e-group of 4, m-split of 4), LDS.128 V reads, shfl reduce.
// ---------------------------------------------------------------------------
__global__ void __launch_bounds__(256, 2) attn_kernel() {
    int win = blockIdx.x, head = blockIdx.y;
    extern __shared__ float sm[];
    float* skT = sm;                      // 16*512
    float* sv  = skT + HDIM * NTOK;       // 512*16
    float* ss  = sv + NTOK * HDIM;        // 16*512
    int tid = threadIdx.x;

    // load K (transposed) and V
    #pragma unroll
    for (int r = 0; r < 2; r++) {
        int n = tid + r * 256;
        int l = tok_of(win, n);
        const float4* kp = (const float4*)(g_qkv + (size_t)l * QKVN + CCH + head * HDIM);
        const float4* vp = (const float4*)(g_qkv + (size_t)l * QKVN + 2 * CCH + head * HDIM);
        #pragma unroll
        for (int j = 0; j < 4; j++) {
            float4 kk = kp[j];
            int e = j * 4;
            skT[(e + 0) * NTOK + n] = kk.x;
            skT[(e + 1) * NTOK + n] = kk.y;
            skT[(e + 2) * NTOK + n] = kk.z;
            skT[(e + 3) * NTOK + n] = kk.w;
            ((float4*)(sv + n * HDIM))[j] = vp[j];
        }
    }
    __syncthreads();

    const float* brow = g_bias + (size_t)head * NTOK * NTOK;
    int qi = tid >> 4;            // 0..15 (fixed per thread)
    int ms2 = tid & 15;           // scores: 2-wide m start
    int msplit = tid & 3;         // PV: m phase
    int eg = (tid >> 2) & 3;      // PV: e group of 4

    for (int qt = 0; qt < NTOK / 16; qt++) {
        int nq = qt * 16 + qi;
        int lq = tok_of(win, nq);

        // Q row in registers (scaled by hd^-0.5 = 0.25)
        const float4* qp = (const float4*)(g_qkv + (size_t)lq * QKVN + head * HDIM);
        float4 t0 = qp[0], t1 = qp[1], t2 = qp[2], t3 = qp[3];
        float qreg[16];
        qreg[0]  = t0.x * .25f; qreg[1]  = t0.y * .25f; qreg[2]  = t0.z * .25f; qreg[3]  = t0.w * .25f;
        qreg[4]  = t1.x * .25f; qreg[5]  = t1.y * .25f; qreg[6]  = t1.z * .25f; qreg[7]  = t1.w * .25f;
        qreg[8]  = t2.x * .25f; qreg[9]  = t2.y * .25f; qreg[10] = t2.z * .25f; qreg[11] = t2.w * .25f;
        qreg[12] = t3.x * .25f; qreg[13] = t3.y * .25f; qreg[14] = t3.z * .25f; qreg[15] = t3.w * .25f;

        const float* bq = brow + (size_t)nq * NTOK;
        float* srow = ss + qi * NTOK;

        // scores: 2 m per step, float2 K reads
        #pragma unroll 2
        for (int it = 0; it < 16; it++) {
            int m = ms2 * 2 + it * 32;
            float dx = 0.f, dy = 0.f;
            #pragma unroll
            for (int e = 0; e < 16; e++) {
                float2 kv = *(const float2*)(skT + e * NTOK + m);
                dx += qreg[e] * kv.x;
                dy += qreg[e] * kv.y;
            }
            float2 bb = *(const float2*)(bq + m);
            float2 o; o.x = dx + bb.x; o.y = dy + bb.y;
            *(float2*)(srow + m) = o;
        }
        __syncthreads();

        // softmax per row: 8 warps x 2 rows
        {
            int warp = tid >> 5, lane = tid & 31;
            #pragma unroll
            for (int r = 0; r < 2; r++) {
                float* row = ss + (warp * 2 + r) * NTOK;
                float mx = -3.0e38f;
                #pragma unroll
                for (int m = lane; m < NTOK; m += 32) mx = fmaxf(mx, row[m]);
                #pragma unroll
                for (int o = 16; o; o >>= 1) mx = fmaxf(mx, __shfl_xor_sync(0xffffffffu, mx, o));
                float sum = 0.f;
                #pragma unroll
                for (int m = lane; m < NTOK; m += 32) {
                    float e = __expf(row[m] - mx);
                    row[m] = e;
                    sum += e;
                }
                #pragma unroll
                for (int o = 16; o; o >>= 1) sum += __shfl_xor_sync(0xffffffffu, sum, o);
                float inv = 1.f / sum;
                #pragma unroll
                for (int m = lane; m < NTOK; m += 32) row[m] *= inv;
            }
        }
        __syncthreads();

        // PV: each thread sums m = msplit::4, 4 e outputs via float4 V reads
        {
            const float* prow = ss + qi * NTOK;
            float ax = 0.f, ay = 0.f, az = 0.f, aw = 0.f;
            #pragma unroll 4
            for (int m = msplit; m < NTOK; m += 4) {
                float p = prow[m];
                float4 vv = *(const float4*)(sv + m * HDIM + eg * 4);
                ax += p * vv.x; ay += p * vv.y; az += p * vv.z; aw += p * vv.w;
            }
            // reduce across msplit (lane bits 0-1)
            ax += __shfl_xor_sync(0xffffffffu, ax, 1);
            ay += __shfl_xor_sync(0xffffffffu, ay, 1);
            az += __shfl_xor_sync(0xffffffffu, az, 1);
            aw += __shfl_xor_sync(0xffffffffu, aw, 1);
            ax += __shfl_xor_sync(0xffffffffu, ax, 2);
            ay += __shfl_xor_sync(0xffffffffu, ay, 2);
            az += __shfl_xor_sync(0xffffffffu, az, 2);
            aw += __shfl_xor_sync(0xffffffffu, aw, 2);
            if (msplit == 0) {
                float4 o = make_float4(ax, ay, az, aw);
                *(float4*)(g_o + (size_t)lq * CCH + head * HDIM + eg * 4) = o;
            }
        }
        __syncthreads();
    }
}

// ---------------------------------------------------------------------------
extern "C" void kernel_launch(void* const* d_in, const int* in_sizes, int n_in,
                              void* d_out, int out_size) {
    const float* x       = (const float*)d_in[0];
    const float* norm1_g = (const float*)d_in[1];
    const float* norm1_b = (const float*)d_in[2];
    const float* qkv_w   = (const float*)d_in[3];
    const float* qkv_b   = (const float*)d_in[4];
    const float* rpbt    = (const float*)d_in[5];
    const float* proj_w  = (const float*)d_in[6];
    const float* proj_b  = (const float*)d_in[7];
    const float* conv1_w = (const float*)d_in[8];
    const float* conv1_b = (const float*)d_in[9];
    const float* conv2_w = (const float*)d_in[10];
    const float* conv2_b = (const float*)d_in[11];
    const float* ca1_w   = (const float*)d_in[12];
    const float* ca1_b   = (const float*)d_in[13];
    const float* ca2_w   = (const float*)d_in[14];
    const float* ca2_b   = (const float*)d_in[15];
    const float* norm2_g = (const float*)d_in[16];
    const float* norm2_b = (const float*)d_in[17];
    const float* fc1_w   = (const float*)d_in[18];
    const float* fc1_b   = (const float*)d_in[19];
    const float* fc2_w   = (const float*)d_in[20];
    const float* fc2_b   = (const float*)d_in[21];
    const int*   rpi     = (const int*)d_in[22];
    float* out = (float*)d_out;

    // pointers to device globals
    float *p_xn, *p_xcf, *p_y1cf, *p_y2cf, *p_w1t, *p_w2t;
    float *p_qkv, *p_o, *p_tmp, *p_h, *p_xmid;
    cudaGetSymbolAddress((void**)&p_xn,   g_xn);
    cudaGetSymbolAddress((void**)&p_xcf,  g_xcf);
    cudaGetSymbolAddress((void**)&p_y1cf, g_y1cf);
    cudaGetSymbolAddress((void**)&p_y2cf, g_y2cf);
    cudaGetSymbolAddress((void**)&p_w1t,  g_w1t);
    cudaGetSymbolAddress((void**)&p_w2t,  g_w2t);
    cudaGetSymbolAddress((void**)&p_qkv,  g_qkv);
    cudaGetSymbolAddress((void**)&p_o,    g_o);
    cudaGetSymbolAddress((void**)&p_tmp,  g_tmp);
    cudaGetSymbolAddress((void**)&p_h,    g_h);
    cudaGetSymbolAddress((void**)&p_xmid, g_xmid);

    // attention kernel needs 96 KB dynamic smem
    static const size_t attn_smem =
        (size_t)(HDIM * NTOK + NTOK * HDIM + 16 * NTOK) * sizeof(float);
    cudaFuncSetAttribute(attn_kernel, cudaFuncAttributeMaxDynamicSharedMemorySize,
                         (int)attn_smem);

    // weight transposes + bias expansion (read inputs only)
    twc_kernel<<<(CMP * CCH * 27 + 255) / 256, 256>>>(conv1_w, p_w1t, CMP, CCH);
    twc_kernel<<<(CCH * CMP * 27 + 255) / 256, 256>>>(conv2_w, p_w2t, CCH, CMP);
    bias_kernel<<<(NTOK * NTOK + 255) / 256, 256>>>(rpi, rpbt);

    // LN1
    ln_kernel<<<LTOK / 8, 256>>>(x, norm1_g, norm1_b, p_xn);

    // channels-first copy for conv branch
    {
        dim3 grid(CCH / 32, LTOK / 32);
        tocf_kernel<<<grid, dim3(32, 8)>>>(p_xn, p_xcf);
    }

    // conv branch: tap-outer implicit GEMM convs (register-staged prefetch)
    {
        dim3 g1(LTOK / 128, CMP / 32);
        convgemm2_kernel<CCH, CMP, 1><<<g1, 256>>>(p_w1t, conv1_b, p_xcf, p_y1cf);
        dim3 g2(LTOK / 128, CCH / 32);
        convgemm2_kernel<CMP, CCH, 0><<<g2, 256>>>(p_w2t, conv2_b, p_y1cf, p_y2cf);
    }
    poolcf_kernel<<<CCH, 256>>>();
    chanatt_kernel<<<1, CCH>>>(ca1_w, ca1_b, ca2_w, ca2_b);

    // QKV GEMM: [32768,96] x [288,96]^T
    {
        dim3 grid((QKVN + 63) / 64, LTOK / 128);
        sgemm128_kernel<0, 0><<<grid, 256>>>(p_xn, qkv_w, qkv_b, nullptr, p_qkv,
                                             LTOK, QKVN, CCH);
    }

    // windowed attention
    {
        dim3 grid(NWIN, HEADS);
        attn_kernel<<<grid, 256, attn_smem>>>();
    }

    // proj GEMM
    {
        dim3 grid((CCH + 63) / 64, LTOK / 128);
        sgemm128_kernel<0, 0><<<grid, 256>>>(p_o, proj_w, proj_b, nullptr, p_tmp,
                                             LTOK, CCH, CCH);
    }

    // fused residual-1 + LN2
    resid_ln_kernel<<<LTOK / 8, 256>>>(x, norm2_g, norm2_b);

    // MLP: fc1 (+GELU) then fc2 (+final residual, straight to output)
    {
        dim3 grid((HID + 63) / 64, LTOK / 128);
        sgemm128_kernel<1, 0><<<grid, 256>>>(p_xn, fc1_w, fc1_b, nullptr, p_h,
                                             LTOK, HID, CCH);
    }
    {
        dim3 grid((CCH + 63) / 64, LTOK / 128);
        sgemm128_kernel<0, 1><<<grid, 256>>>(p_h, fc2_w, fc2_b, p_xmid, out,
                                             LTOK, CCH, HID);
    }
}

// round 13
// speedup vs baseline: 1.4522x; 1.0016x over previous
#include <cuda_runtime.h>
#include <math.h>

// ---------------------------------------------------------------------------
// Fixed problem shapes (from reference setup_inputs)
// ---------------------------------------------------------------------------
#define LTOK  32768      // B * D*H*W
#define CCH   96
#define DD    8
#define HH    64
#define WW    64
#define NWIN  64         // (D/8)*(H/8)*(W/8) = 1*8*8
#define NTOK  512        // 8^3 tokens per window
#define HEADS 6
#define HDIM  16
#define CMP   32         // C/3
#define SQZ   3          // C/30
#define HID   384        // 4C
#define QKVN  288        // 3C

// ---------------------------------------------------------------------------
// Scratch (device globals; no allocation anywhere)
// ---------------------------------------------------------------------------
__device__ float g_xn  [LTOK * CCH];          // LN1 out, later reused for LN2 out
__device__ float g_xcf [CCH * LTOK];          // LN1 out, channels-first
__device__ float g_y1cf[CMP * LTOK];          // conv1+gelu out, channels-first
__device__ float g_y2cf[CCH * LTOK];          // conv2 out, channels-first
__device__ float g_w1t [27 * CMP * CCH];      // conv1 W as [tap][co][ci]
__device__ float g_w2t [27 * CCH * CMP];      // conv2 W as [tap][co][ci]
__device__ float g_pool[CCH];
__device__ float g_att [CCH];                 // channel attention scale
__device__ float g_bias[HEADS * NTOK * NTOK]; // rpbt[rpi] expanded
__device__ float g_qkv [LTOK * QKVN];
__device__ float g_o   [LTOK * CCH];          // attention out (token order)
__device__ float g_xmid[LTOK * CCH];
__device__ float g_h   [LTOK * HID];          // MLP hidden
__device__ float g_tmp [LTOK * CCH];          // proj GEMM out

// ---------------------------------------------------------------------------
__device__ __forceinline__ float gelu_f(float x) {
    return 0.5f * x * (1.f + erff(x * 0.70710678118654752f));
}

// token index for (window, in-window position); window depth count == 1
__device__ __forceinline__ int tok_of(int win, int n) {
    int wh = win >> 3, ww = win & 7;
    int nd = n >> 6, nh = (n >> 3) & 7, nw = n & 7;
    return nd * 4096 + (wh * 8 + nh) * 64 + (ww * 8 + nw);
}

// ---------------------------------------------------------------------------
// LayerNorm over C=96: one warp per row
// ---------------------------------------------------------------------------
__global__ void ln_kernel(const float* __restrict__ x, const float* __restrict__ g,
                          const float* __restrict__ b, float* __restrict__ y) {
    int warp = threadIdx.x >> 5, lane = threadIdx.x & 31;
    int row = blockIdx.x * 8 + warp;
    const float* xr = x + row * CCH;
    float v0 = xr[lane], v1 = xr[lane + 32], v2 = xr[lane + 64];
    float s = v0 + v1 + v2;
    #pragma unroll
    for (int o = 16; o; o >>= 1) s += __shfl_xor_sync(0xffffffffu, s, o);
    float mu = s * (1.f / 96.f);
    float d0 = v0 - mu, d1 = v1 - mu, d2 = v2 - mu;
    float q = d0 * d0 + d1 * d1 + d2 * d2;
    #pragma unroll
    for (int o = 16; o; o >>= 1) q += __shfl_xor_sync(0xffffffffu, q, o);
    float rs = rsqrtf(q * (1.f / 96.f) + 1e-5f);
    float* yr = y + row * CCH;
    yr[lane]      = d0 * rs * g[lane]      + b[lane];
    yr[lane + 32] = d1 * rs * g[lane + 32] + b[lane + 32];
    yr[lane + 64] = d2 * rs * g[lane + 64] + b[lane + 64];
}

// ---------------------------------------------------------------------------
// Fused residual-1 + LayerNorm2: one warp per row.
//   xmid = x + proj_out + conv_out * att[c] * 0.01 ;  xn = LN(xmid)
// ---------------------------------------------------------------------------
__global__ void resid_ln_kernel(const float* __restrict__ x,
                                const float* __restrict__ g, const float* __restrict__ b) {
    int warp = threadIdx.x >> 5, lane = threadIdx.x & 31;
    int row = blockIdx.x * 8 + warp;
    int c0 = lane, c1 = lane + 32, c2 = lane + 64;
    size_t base = (size_t)row * CCH;
    float v0 = x[base + c0] + g_tmp[base + c0] + g_y2cf[(size_t)c0 * LTOK + row] * g_att[c0] * 0.01f;
    float v1 = x[base + c1] + g_tmp[base + c1] + g_y2cf[(size_t)c1 * LTOK + row] * g_att[c1] * 0.01f;
    float v2 = x[base + c2] + g_tmp[base + c2] + g_y2cf[(size_t)c2 * LTOK + row] * g_att[c2] * 0.01f;
    g_xmid[base + c0] = v0; g_xmid[base + c1] = v1; g_xmid[base + c2] = v2;
    float s = v0 + v1 + v2;
    #pragma unroll
    for (int o = 16; o; o >>= 1) s += __shfl_xor_sync(0xffffffffu, s, o);
    float mu = s * (1.f / 96.f);
    float d0 = v0 - mu, d1 = v1 - mu, d2 = v2 - mu;
    float q = d0 * d0 + d1 * d1 + d2 * d2;
    #pragma unroll
    for (int o = 16; o; o >>= 1) q += __shfl_xor_sync(0xffffffffu, q, o);
    float rs = rsqrtf(q * (1.f / 96.f) + 1e-5f);
    g_xn[base + c0] = d0 * rs * g[c0] + b[c0];
    g_xn[base + c1] = d1 * rs * g[c1] + b[c1];
    g_xn[base + c2] = d2 * rs * g[c2] + b[c2];
}

// ---------------------------------------------------------------------------
// Transpose [L][96] -> [96][L]  (32x32 tiles)
// ---------------------------------------------------------------------------
__global__ void tocf_kernel(const float* __restrict__ src, float* __restrict__ dst) {
    __shared__ float t[32][33];
    int c0 = blockIdx.x * 32, l0 = blockIdx.y * 32;
    int tx = threadIdx.x, ty = threadIdx.y;   // 32 x 8
    #pragma unroll
    for (int r = 0; r < 4; r++)
        t[ty + r * 8][tx] = src[(size_t)(l0 + ty + r * 8) * CCH + c0 + tx];
    __syncthreads();
    #pragma unroll
    for (int r = 0; r < 4; r++)
        dst[(size_t)(c0 + ty + r * 8) * LTOK + l0 + tx] = t[tx][ty + r * 8];
}

// ---------------------------------------------------------------------------
// Conv weight transpose: [CO][CI][27] -> [tap][CO][CI]
// ---------------------------------------------------------------------------
__global__ void twc_kernel(const float* __restrict__ w, float* __restrict__ dst,
                           int CO_, int CI_) {
    int i = blockIdx.x * blockDim.x + threadIdx.x;
    if (i >= CO_ * CI_ * 27) return;
    int co = i / (CI_ * 27);
    int rem = i - co * CI_ * 27;
    int ci = rem / 27;
    int tap = rem - ci * 27;
    dst[((size_t)tap * CO_ + co) * CI_ + ci] = w[i];
}

// ---------------------------------------------------------------------------
// Staged load for conv iteration t (t indexes the flattened (tap, kc) loop):
// each thread loads its 8 A-gather values and 2 B values into registers.
// ---------------------------------------------------------------------------
template <int CIN, int CO>
__device__ __forceinline__ void conv_stage_load(
    int t, int tid, int d, int h0, int n0,
    const float* __restrict__ Wt, const float* __restrict__ xcf,
    float* __restrict__ sa, float* __restrict__ sb) {
    const int KCI = CIN / 16;
    int tap = t / KCI;
    int kc = (t - tap * KCI) * 16;
    int td = tap / 9;
    int t2 = tap - td * 9;
    int th = t2 / 3;
    int tw = t2 - th * 3;
    int dd = d + td - 1;
    bool okd = (unsigned)dd < DD;
    int hb = h0 + th - 1;
    bool okh0 = okd && ((unsigned)hb < HH);
    bool okh1 = okd && ((unsigned)(hb + 1) < HH);
    int baseL = dd * 4096 + hb * 64 + (tw - 1);
    const float* wtap = Wt + (size_t)tap * CO * CIN;
    #pragma unroll
    for (int rr = 0; rr < 8; rr++) {
        int i = rr * 256 + tid;
        int kk = i >> 7, mm = i & 127;
        int w = mm & 63;
        bool ok = ((mm >> 6) ? okh1 : okh0) && ((unsigned)(w + tw - 1) < WW);
        sa[rr] = ok ? xcf[(size_t)(kc + kk) * LTOK + baseL + mm] : 0.f;
    }
    #pragma unroll
    for (int rr = 0; rr < 2; rr++) {
        int i = rr * 256 + tid;
        int nn = i >> 4, kk = i & 15;
        sb[rr] = wtap[(size_t)(n0 + nn) * CIN + kc + kk];
    }
}

// ---------------------------------------------------------------------------
// Tap-outer implicit-GEMM 3x3x3 'SAME' conv, channels-first.
// 2-stage smem double buffering: ONE barrier per k-iteration; tile t+1 is
// written to the alternate buffer while tile t is consumed.
// Tile: 128 M (two (d,h) rows of w) x 32 N.  256 threads, 4x4 per thread.
// ---------------------------------------------------------------------------
template <int CIN, int CO, int ACT>
__global__ void __launch_bounds__(256, 2)
convgemm2_kernel(const float* __restrict__ Wt,
                 const float* __restrict__ bias,
                 const float* __restrict__ xcf,
                 float* __restrict__ ycf) {
    __shared__ float As[2][16][132];
    __shared__ float Bs[2][16][36];
    int tid = threadIdx.x;
    int m0 = blockIdx.x * 128;           // two w-rows: (d, h0) and (d, h0+1)
    int n0 = blockIdx.y * 32;
    int d = m0 >> 12;
    int h0 = (m0 >> 6) & 63;
    int tx = tid & 7, ty = tid >> 3;     // tx: 4 N-cols, ty: 4 M-rows

    float acc[4][4] = {};
    const int T = 27 * (CIN / 16);

    float sa[8], sb[2];
    // prologue: tile 0 -> buf 0, stage tile 1 in registers
    conv_stage_load<CIN, CO>(0, tid, d, h0, n0, Wt, xcf, sa, sb);
    #pragma unroll
    for (int rr = 0; rr < 8; rr++) {
        int i = rr * 256 + tid;
        As[0][i >> 7][i & 127] = sa[rr];
    }
    #pragma unroll
    for (int rr = 0; rr < 2; rr++) {
        int i = rr * 256 + tid;
        Bs[0][i & 15][i >> 4] = sb[rr];
    }
    conv_stage_load<CIN, CO>(1, tid, d, h0, n0, Wt, xcf, sa, sb);
    __syncthreads();

    for (int t = 0; t < T; t++) {
        int cur = t & 1;
        // store tile t+1 into the other buffer; then issue tile t+2's loads
        if (t + 1 < T) {
            int nxt = cur ^ 1;
            #pragma unroll
            for (int rr = 0; rr < 8; rr++) {
                int i = rr * 256 + tid;
                As[nxt][i >> 7][i & 127] = sa[rr];
            }
            #pragma unroll
            for (int rr = 0; rr < 2; rr++) {
                int i = rr * 256 + tid;
                Bs[nxt][i & 15][i >> 4] = sb[rr];
            }
            if (t + 2 < T)
                conv_stage_load<CIN, CO>(t + 2, tid, d, h0, n0, Wt, xcf, sa, sb);
        }

        #pragma unroll
        for (int kk = 0; kk < 16; kk++) {
            float4 a = *(const float4*)&As[cur][kk][ty * 4];
            float4 b = *(const float4*)&Bs[cur][kk][tx * 4];
            float av[4] = {a.x, a.y, a.z, a.w};
            float bv[4] = {b.x, b.y, b.z, b.w};
            #pragma unroll
            for (int i = 0; i < 4; i++)
                #pragma unroll
                for (int j = 0; j < 4; j++) acc[i][j] += av[i] * bv[j];
        }
        __syncthreads();
    }

    // epilogue: float4 store per output channel (m-contiguous)
    int m = m0 + ty * 4;
    #pragma unroll
    for (int j = 0; j < 4; j++) {
        int n = n0 + tx * 4 + j;
        float bb = bias[n];
        float4 v;
        v.x = acc[0][j] + bb; v.y = acc[1][j] + bb;
        v.z = acc[2][j] + bb; v.w = acc[3][j] + bb;
        if (ACT == 1) { v.x = gelu_f(v.x); v.y = gelu_f(v.y); v.z = gelu_f(v.z); v.w = gelu_f(v.w); }
        *(float4*)(ycf + (size_t)n * LTOK + m) = v;
    }
}

// ---------------------------------------------------------------------------
// Channel attention: pooled reduce on channels-first conv output + squeeze-excite
// ---------------------------------------------------------------------------
__global__ void poolcf_kernel() {
    __shared__ float red[8];
    int c = blockIdx.x;
    const float* row = g_y2cf + (size_t)c * LTOK;
    float s = 0.f;
    for (int l = threadIdx.x; l < LTOK; l += 256) s += row[l];
    #pragma unroll
    for (int o = 16; o; o >>= 1) s += __shfl_xor_sync(0xffffffffu, s, o);
    if ((threadIdx.x & 31) == 0) red[threadIdx.x >> 5] = s;
    __syncthreads();
    if (threadIdx.x == 0) {
        float t = 0.f;
        #pragma unroll
        for (int i = 0; i < 8; i++) t += red[i];
        g_pool[c] = t;
    }
}

__global__ void chanatt_kernel(const float* __restrict__ ca1_w, const float* __restrict__ ca1_b,
                               const float* __restrict__ ca2_w, const float* __restrict__ ca2_b) {
    __shared__ float p[CCH];
    __shared__ float t[SQZ];
    int c = threadIdx.x;
    p[c] = g_pool[c] * (1.f / (float)LTOK);
    __syncthreads();
    if (c < SQZ) {
        float s = ca1_b[c];
        for (int i = 0; i < CCH; i++) s += ca1_w[c * CCH + i] * p[i];
        t[c] = fmaxf(s, 0.f);
    }
    __syncthreads();
    float s = ca2_b[c];
    #pragma unroll
    for (int i = 0; i < SQZ; i++) s += ca2_w[c * SQZ + i] * t[i];
    g_att[c] = 1.f / (1.f + expf(-s));
}

// ---------------------------------------------------------------------------
// Relative position bias expand: bias[h][n][m] = rpbt[rpi[n][m]][h]
// ---------------------------------------------------------------------------
__global__ void bias_kernel(const int* __restrict__ rpi, const float* __restrict__ rpbt) {
    int nm = blockIdx.x * blockDim.x + threadIdx.x;
    if (nm >= NTOK * NTOK) return;
    int rp = rpi[nm];
    #pragma unroll
    for (int hh = 0; hh < HEADS; hh++)
        g_bias[hh * NTOK * NTOK + nm] = rpbt[rp * HEADS + hh];
}

// ---------------------------------------------------------------------------
// SGEMM 128x64x16, 256 threads, 8x4 per thread, float4 smem paths,
// 2-stage smem double buffering: ONE barrier per k-iteration.
//   C[M,N] = A[M,K] @ B[N,K]^T + bias[N]  (+GELU, +residual)
// M must be a multiple of 128; N a multiple of 4; K a multiple of 16.
// ---------------------------------------------------------------------------
template <int ACT, int RESID>
__global__ void __launch_bounds__(256, 2)
sgemm128_kernel(const float* __restrict__ A, const float* __restrict__ B,
                const float* __restrict__ bias, const float* __restrict__ resid,
                float* __restrict__ C, int M, int N, int K) {
    __shared__ float As[2][16][132];
    __shared__ float Bs[2][16][68];
    int tid = threadIdx.x;
    int m0 = blockIdx.y * 128, n0 = blockIdx.x * 64;
    int tx = tid & 15, ty = tid >> 4;        // tx: 4 N-cols, ty: 8 M-rows

    int la_m = tid >> 2;                     // 0..63
    int la_k = (tid & 3) * 4;
    bool bn_ok = (n0 + la_m < N);
    float acc[8][4] = {};

    const int NK = K / 16;
    float4 a_pre0, a_pre1, b_pre;

    // prologue: tile 0 -> buf 0, stage tile 1 in registers
    a_pre0 = *(const float4*)(A + (size_t)(m0 + la_m) * K + la_k);
    a_pre1 = *(const float4*)(A + (size_t)(m0 + la_m + 64) * K + la_k);
    b_pre = make_float4(0.f, 0.f, 0.f, 0.f);
    if (bn_ok) b_pre = *(const float4*)(B + (size_t)(n0 + la_m) * K + la_k);
    As[0][la_k + 0][la_m] = a_pre0.x;
    As[0][la_k + 1][la_m] = a_pre0.y;
    As[0][la_k + 2][la_m] = a_pre0.z;
    As[0][la_k + 3][la_m] = a_pre0.w;
    As[0][la_k + 0][la_m + 64] = a_pre1.x;
    As[0][la_k + 1][la_m + 64] = a_pre1.y;
    As[0][la_k + 2][la_m + 64] = a_pre1.z;
    As[0][la_k + 3][la_m + 64] = a_pre1.w;
    Bs[0][la_k + 0][la_m] = b_pre.x;
    Bs[0][la_k + 1][la_m] = b_pre.y;
    Bs[0][la_k + 2][la_m] = b_pre.z;
    Bs[0][la_k + 3][la_m] = b_pre.w;
    if (NK > 1) {
        int kn = 16 + la_k;
        a_pre0 = *(const float4*)(A + (size_t)(m0 + la_m) * K + kn);
        a_pre1 = *(const float4*)(A + (size_t)(m0 + la_m + 64) * K + kn);
        if (bn_ok) b_pre = *(const float4*)(B + (size_t)(n0 + la_m) * K + kn);
    }
    __syncthreads();

    for (int t = 0; t < NK; t++) {
        int cur = t & 1;
        if (t + 1 < NK) {
            int nxt = cur ^ 1;
            As[nxt][la_k + 0][la_m] = a_pre0.x;
            As[nxt][la_k + 1][la_m] = a_pre0.y;
            As[nxt][la_k + 2][la_m] = a_pre0.z;
            As[nxt][la_k + 3][la_m] = a_pre0.w;
            As[nxt][la_k + 0][la_m + 64] = a_pre1.x;
            As[nxt][la_k + 1][la_m + 64] = a_pre1.y;
            As[nxt][la_k + 2][la_m + 64] = a_pre1.z;
            As[nxt][la_k + 3][la_m + 64] = a_pre1.w;
            Bs[nxt][la_k + 0][la_m] = b_pre.x;
            Bs[nxt][la_k + 1][la_m] = b_pre.y;
            Bs[nxt][la_k + 2][la_m] = b_pre.z;
            Bs[nxt][la_k + 3][la_m] = b_pre.w;
            if (t + 2 < NK) {
                int kn = (t + 2) * 16 + la_k;
                a_pre0 = *(const float4*)(A + (size_t)(m0 + la_m) * K + kn);
                a_pre1 = *(const float4*)(A + (size_t)(m0 + la_m + 64) * K + kn);
                if (bn_ok) b_pre = *(const float4*)(B + (size_t)(n0 + la_m) * K + kn);
            }
        }

        #pragma unroll
        for (int kk = 0; kk < 16; kk++) {
            float4 a0 = *(const float4*)&As[cur][kk][ty * 8];
            float4 a1 = *(const float4*)&As[cur][kk][ty * 8 + 4];
            float4 b0 = *(const float4*)&Bs[cur][kk][tx * 4];
            float av[8] = {a0.x, a0.y, a0.z, a0.w, a1.x, a1.y, a1.z, a1.w};
            float bv[4] = {b0.x, b0.y, b0.z, b0.w};
            #pragma unroll
            for (int i = 0; i < 8; i++)
                #pragma unroll
                for (int j = 0; j < 4; j++) acc[i][j] += av[i] * bv[j];
        }
        __syncthreads();
    }

    int n = n0 + tx * 4;
    if (n < N) {
        float4 bb = *(const float4*)(bias + n);
        #pragma unroll
        for (int i = 0; i < 8; i++) {
            int m = m0 + ty * 8 + i;
            float4 v;
            v.x = acc[i][0] + bb.x; v.y = acc[i][1] + bb.y;
            v.z = acc[i][2] + bb.z; v.w = acc[i][3] + bb.w;
            if (ACT == 1) {
                v.x = gelu_f(v.x); v.y = gelu_f(v.y);
                v.z = gelu_f(v.z); v.w = gelu_f(v.w);
            }
            if (RESID == 1) {
                float4 rr = *(const float4*)(resid + (size_t)m * N + n);
                v.x += rr.x; v.y += rr.y; v.z += rr.z; v.w += rr.w;
            }
            *(float4*)(C + (size_t)m * N + n) = v;
        }
    }
}

// ---------------------------------------------------------------------------
// Window attention: one block per (window, head), 256 threads.
// skT[16][512] (K transposed), sv[512][16], ss[16][512].
// Scores: fixed qi per thread, Q in registers, float2 K reads.
// PV: (qi, e-group of 4, m-split of 4), LDS.128 V reads, shfl reduce.
// ---------------------------------------------------------------------------
__global__ void __launch_bounds__(256, 2) attn_kernel() {
    int win = blockIdx.x, head = blockIdx.y;
    extern __shared__ float sm[];
    float* skT = sm;                      // 16*512
    float* sv  = skT + HDIM * NTOK;       // 512*16
    float* ss  = sv + NTOK * HDIM;        // 16*512
    int tid = threadIdx.x;

    // load K (transposed) and V
    #pragma unroll
    for (int r = 0; r < 2; r++) {
        int n = tid + r * 256;
        int l = tok_of(win, n);
        const float4* kp = (const float4*)(g_qkv + (size_t)l * QKVN + CCH + head * HDIM);
        const float4* vp = (const float4*)(g_qkv + (size_t)l * QKVN + 2 * CCH + head * HDIM);
        #pragma unroll
        for (int j = 0; j < 4; j++) {
            float4 kk = kp[j];
            int e = j * 4;
            skT[(e + 0) * NTOK + n] = kk.x;
            skT[(e + 1) * NTOK + n] = kk.y;
            skT[(e + 2) * NTOK + n] = kk.z;
            skT[(e + 3) * NTOK + n] = kk.w;
            ((float4*)(sv + n * HDIM))[j] = vp[j];
        }
    }
    __syncthreads();

    const float* brow = g_bias + (size_t)head * NTOK * NTOK;
    int qi = tid >> 4;            // 0..15 (fixed per thread)
    int ms2 = tid & 15;           // scores: 2-wide m start
    int msplit = tid & 3;         // PV: m phase
    int eg = (tid >> 2) & 3;      // PV: e group of 4

    for (int qt = 0; qt < NTOK / 16; qt++) {
        int nq = qt * 16 + qi;
        int lq = tok_of(win, nq);

        // Q row in registers (scaled by hd^-0.5 = 0.25)
        const float4* qp = (const float4*)(g_qkv + (size_t)lq * QKVN + head * HDIM);
        float4 t0 = qp[0], t1 = qp[1], t2 = qp[2], t3 = qp[3];
        float qreg[16];
        qreg[0]  = t0.x * .25f; qreg[1]  = t0.y * .25f; qreg[2]  = t0.z * .25f; qreg[3]  = t0.w * .25f;
        qreg[4]  = t1.x * .25f; qreg[5]  = t1.y * .25f; qreg[6]  = t1.z * .25f; qreg[7]  = t1.w * .25f;
        qreg[8]  = t2.x * .25f; qreg[9]  = t2.y * .25f; qreg[10] = t2.z * .25f; qreg[11] = t2.w * .25f;
        qreg[12] = t3.x * .25f; qreg[13] = t3.y * .25f; qreg[14] = t3.z * .25f; qreg[15] = t3.w * .25f;

        const float* bq = brow + (size_t)nq * NTOK;
        float* srow = ss + qi * NTOK;

        // scores: 2 m per step, float2 K reads
        #pragma unroll 2
        for (int it = 0; it < 16; it++) {
            int m = ms2 * 2 + it * 32;
            float dx = 0.f, dy = 0.f;
            #pragma unroll
            for (int e = 0; e < 16; e++) {
                float2 kv = *(const float2*)(skT + e * NTOK + m);
                dx += qreg[e] * kv.x;
                dy += qreg[e] * kv.y;
            }
            float2 bb = *(const float2*)(bq + m);
            float2 o; o.x = dx + bb.x; o.y = dy + bb.y;
            *(float2*)(srow + m) = o;
        }
        __syncthreads();

        // softmax per row: 8 warps x 2 rows
        {
            int warp = tid >> 5, lane = tid & 31;
            #pragma unroll
            for (int r = 0; r < 2; r++) {
                float* row = ss + (warp * 2 + r) * NTOK;
                float mx = -3.0e38f;
                #pragma unroll
                for (int m = lane; m < NTOK; m += 32) mx = fmaxf(mx, row[m]);
                #pragma unroll
                for (int o = 16; o; o >>= 1) mx = fmaxf(mx, __shfl_xor_sync(0xffffffffu, mx, o));
                float sum = 0.f;
                #pragma unroll
                for (int m = lane; m < NTOK; m += 32) {
                    float e = __expf(row[m] - mx);
                    row[m] = e;
                    sum += e;
                }
                #pragma unroll
                for (int o = 16; o; o >>= 1) sum += __shfl_xor_sync(0xffffffffu, sum, o);
                float inv = 1.f / sum;
                #pragma unroll
                for (int m = lane; m < NTOK; m += 32) row[m] *= inv;
            }
        }
        __syncthreads();

        // PV: each thread sums m = msplit::4, 4 e outputs via float4 V reads
        {
            const float* prow = ss + qi * NTOK;
            float ax = 0.f, ay = 0.f, az = 0.f, aw = 0.f;
            #pragma unroll 4
            for (int m = msplit; m < NTOK; m += 4) {
                float p = prow[m];
                float4 vv = *(const float4*)(sv + m * HDIM + eg * 4);
                ax += p * vv.x; ay += p * vv.y; az += p * vv.z; aw += p * vv.w;
            }
            // reduce across msplit (lane bits 0-1)
            ax += __shfl_xor_sync(0xffffffffu, ax, 1);
            ay += __shfl_xor_sync(0xffffffffu, ay, 1);
            az += __shfl_xor_sync(0xffffffffu, az, 1);
            aw += __shfl_xor_sync(0xffffffffu, aw, 1);
            ax += __shfl_xor_sync(0xffffffffu, ax, 2);
            ay += __shfl_xor_sync(0xffffffffu, ay, 2);
            az += __shfl_xor_sync(0xffffffffu, az, 2);
            aw += __shfl_xor_sync(0xffffffffu, aw, 2);
            if (msplit == 0) {
                float4 o = make_float4(ax, ay, az, aw);
                *(float4*)(g_o + (size_t)lq * CCH + head * HDIM + eg * 4) = o;
            }
        }
        __syncthreads();
    }
}

// ---------------------------------------------------------------------------
extern "C" void kernel_launch(void* const* d_in, const int* in_sizes, int n_in,
                              void* d_out, int out_size) {
    const float* x       = (const float*)d_in[0];
    const float* norm1_g = (const float*)d_in[1];
    const float* norm1_b = (const float*)d_in[2];
    const float* qkv_w   = (const float*)d_in[3];
    const float* qkv_b   = (const float*)d_in[4];
    const float* rpbt    = (const float*)d_in[5];
    const float* proj_w  = (const float*)d_in[6];
    const float* proj_b  = (const float*)d_in[7];
    const float* conv1_w = (const float*)d_in[8];
    const float* conv1_b = (const float*)d_in[9];
    const float* conv2_w = (const float*)d_in[10];
    const float* conv2_b = (const float*)d_in[11];
    const float* ca1_w   = (const float*)d_in[12];
    const float* ca1_b   = (const float*)d_in[13];
    const float* ca2_w   = (const float*)d_in[14];
    const float* ca2_b   = (const float*)d_in[15];
    const float* norm2_g = (const float*)d_in[16];
    const float* norm2_b = (const float*)d_in[17];
    const float* fc1_w   = (const float*)d_in[18];
    const float* fc1_b   = (const float*)d_in[19];
    const float* fc2_w   = (const float*)d_in[20];
    const float* fc2_b   = (const float*)d_in[21];
    const int*   rpi     = (const int*)d_in[22];
    float* out = (float*)d_out;

    // pointers to device globals
    float *p_xn, *p_xcf, *p_y1cf, *p_y2cf, *p_w1t, *p_w2t;
    float *p_qkv, *p_o, *p_tmp, *p_h, *p_xmid;
    cudaGetSymbolAddress((void**)&p_xn,   g_xn);
    cudaGetSymbolAddress((void**)&p_xcf,  g_xcf);
    cudaGetSymbolAddress((void**)&p_y1cf, g_y1cf);
    cudaGetSymbolAddress((void**)&p_y2cf, g_y2cf);
    cudaGetSymbolAddress((void**)&p_w1t,  g_w1t);
    cudaGetSymbolAddress((void**)&p_w2t,  g_w2t);
    cudaGetSymbolAddress((void**)&p_qkv,  g_qkv);
    cudaGetSymbolAddress((void**)&p_o,    g_o);
    cudaGetSymbolAddress((void**)&p_tmp,  g_tmp);
    cudaGetSymbolAddress((void**)&p_h,    g_h);
    cudaGetSymbolAddress((void**)&p_xmid, g_xmid);

    // attention kernel needs 96 KB dynamic smem
    static const size_t attn_smem =
        (size_t)(HDIM * NTOK + NTOK * HDIM + 16 * NTOK) * sizeof(float);
    cudaFuncSetAttribute(attn_kernel, cudaFuncAttributeMaxDynamicSharedMemorySize,
                         (int)attn_smem);

    // weight transposes + bias expansion (read inputs only)
    twc_kernel<<<(CMP * CCH * 27 + 255) / 256, 256>>>(conv1_w, p_w1t, CMP, CCH);
    twc_kernel<<<(CCH * CMP * 27 + 255) / 256, 256>>>(conv2_w, p_w2t, CCH, CMP);
    bias_kernel<<<(NTOK * NTOK + 255) / 256, 256>>>(rpi, rpbt);

    // LN1
    ln_kernel<<<LTOK / 8, 256>>>(x, norm1_g, norm1_b, p_xn);

    // channels-first copy for conv branch
    {
        dim3 grid(CCH / 32, LTOK / 32);
        tocf_kernel<<<grid, dim3(32, 8)>>>(p_xn, p_xcf);
    }

    // conv branch: tap-outer implicit GEMM convs (double-buffered)
    {
        dim3 g1(LTOK / 128, CMP / 32);
        convgemm2_kernel<CCH, CMP, 1><<<g1, 256>>>(p_w1t, conv1_b, p_xcf, p_y1cf);
        dim3 g2(LTOK / 128, CCH / 32);
        convgemm2_kernel<CMP, CCH, 0><<<g2, 256>>>(p_w2t, conv2_b, p_y1cf, p_y2cf);
    }
    poolcf_kernel<<<CCH, 256>>>();
    chanatt_kernel<<<1, CCH>>>(ca1_w, ca1_b, ca2_w, ca2_b);

    // QKV GEMM: [32768,96] x [288,96]^T
    {
        dim3 grid((QKVN + 63) / 64, LTOK / 128);
        sgemm128_kernel<0, 0><<<grid, 256>>>(p_xn, qkv_w, qkv_b, nullptr, p_qkv,
                                             LTOK, QKVN, CCH);
    }

    // windowed attention
    {
        dim3 grid(NWIN, HEADS);
        attn_kernel<<<grid, 256, attn_smem>>>();
    }

    // proj GEMM
    {
        dim3 grid((CCH + 63) / 64, LTOK / 128);
        sgemm128_kernel<0, 0><<<grid, 256>>>(p_o, proj_w, proj_b, nullptr, p_tmp,
                                             LTOK, CCH, CCH);
    }

    // fused residual-1 + LN2
    resid_ln_kernel<<<LTOK / 8, 256>>>(x, norm2_g, norm2_b);

    // MLP: fc1 (+GELU) then fc2 (+final residual, straight to output)
    {
        dim3 grid((HID + 63) / 64, LTOK / 128);
        sgemm128_kernel<1, 0><<<grid, 256>>>(p_xn, fc1_w, fc1_b, nullptr, p_h,
                                             LTOK, HID, CCH);
    }
    {
        dim3 grid((CCH + 63) / 64, LTOK / 128);
        sgemm128_kernel<0, 1><<<grid, 256>>>(p_h, fc2_w, fc2_b, p_xmid, out,
                                             LTOK, CCH, HID);
    }
}